// round 5
// baseline (speedup 1.0000x reference)
#include <cuda_runtime.h>
#include <cuda_bf16.h>
#include <math.h>

#define B_SZ 256
#define D_SZ 512

// ---------------- scratch (device globals; no allocation allowed) ----------
__device__ float g_q[B_SZ * D_SZ];
__device__ float g_k[B_SZ * D_SZ];
__device__ float g_v[B_SZ * D_SZ];
__device__ float g_o[B_SZ * D_SZ];
__device__ float g_it[B_SZ];
__device__ float g_ft[B_SZ];
__device__ float g_ht[B_SZ * D_SZ];

// ---------------- projection GEMM: Y[256,512] = X[256,512] @ W[512,512]^T --
// BM=32, BN=64, BK=16, 256 threads, each computes 2x4. Double-buffered smem.
// grid (8,8,4) = 256 blocks -> better SM coverage than the old 64x64 (128 blocks).
// blockIdx.z selects {Wq,Wk,Wv,Wo}; z==3 fuses bias + sigmoid.
#define BM 32
#define BN 64
#define BK 16

__global__ __launch_bounds__(256) void proj_gemm(
    const float* __restrict__ X,
    const float* __restrict__ Wq, const float* __restrict__ Wk,
    const float* __restrict__ Wv, const float* __restrict__ Wo,
    const float* __restrict__ Wo_b)
{
    const float* W;
    float* Y;
    bool act = false;
    switch (blockIdx.z) {
        case 0: W = Wq; Y = g_q; break;
        case 1: W = Wk; Y = g_k; break;
        case 2: W = Wv; Y = g_v; break;
        default: W = Wo; Y = g_o; act = true; break;
    }

    __shared__ __align__(16) float As[2][BK][BM];   // 4 KB
    __shared__ __align__(16) float Bs[2][BK][BN];   // 8 KB

    const int tid = threadIdx.x;
    const int m0  = blockIdx.y * BM;
    const int n0  = blockIdx.x * BN;

    // A staging: 32x16 floats = 512 -> float2 per thread
    const int ar = tid >> 3;          // 0..31
    const int ac = (tid & 7) * 2;     // 0,2,..,14
    // B staging: 64x16 floats = 1024 -> float4 per thread
    const int br = tid >> 2;          // 0..63
    const int bc = (tid & 3) * 4;     // 0,4,8,12

    const float* Aptr = X + (size_t)(m0 + ar) * D_SZ + ac;
    const float* Bptr = W + (size_t)(n0 + br) * D_SZ + bc;

    // preload tile 0
    {
        float2 a = *(const float2*)Aptr;
        float4 b = *(const float4*)Bptr;
        As[0][ac + 0][ar] = a.x; As[0][ac + 1][ar] = a.y;
        Bs[0][bc + 0][br] = b.x; Bs[0][bc + 1][br] = b.y;
        Bs[0][bc + 2][br] = b.z; Bs[0][bc + 3][br] = b.w;
    }
    __syncthreads();

    const int ty = tid >> 4;   // 0..15 -> m pair
    const int tx = tid & 15;   // 0..15 -> n quad
    float acc[2][4] = {};

    const int KT = D_SZ / BK;  // 32
    int buf = 0;
    for (int t = 0; t < KT; ++t) {
        float2 na; float4 nb;
        if (t + 1 < KT) {
            na = *(const float2*)(Aptr + (t + 1) * BK);
            nb = *(const float4*)(Bptr + (t + 1) * BK);
        }
        #pragma unroll
        for (int kk = 0; kk < BK; ++kk) {
            float2 av = *(const float2*)&As[buf][kk][ty * 2];
            float4 bv = *(const float4*)&Bs[buf][kk][tx * 4];
            acc[0][0] += av.x * bv.x; acc[0][1] += av.x * bv.y;
            acc[0][2] += av.x * bv.z; acc[0][3] += av.x * bv.w;
            acc[1][0] += av.y * bv.x; acc[1][1] += av.y * bv.y;
            acc[1][2] += av.y * bv.z; acc[1][3] += av.y * bv.w;
        }
        if (t + 1 < KT) {
            int nbuf = buf ^ 1;
            As[nbuf][ac + 0][ar] = na.x; As[nbuf][ac + 1][ar] = na.y;
            Bs[nbuf][bc + 0][br] = nb.x; Bs[nbuf][bc + 1][br] = nb.y;
            Bs[nbuf][bc + 2][br] = nb.z; Bs[nbuf][bc + 3][br] = nb.w;
        }
        __syncthreads();
        buf ^= 1;
    }

    const int row = m0 + ty * 2;
    const int col = n0 + tx * 4;
    #pragma unroll
    for (int i = 0; i < 2; ++i) {
        float4 r;
        r.x = acc[i][0]; r.y = acc[i][1]; r.z = acc[i][2]; r.w = acc[i][3];
        if (act) {
            r.x = 1.0f / (1.0f + __expf(-(r.x + Wo_b[col + 0])));
            r.y = 1.0f / (1.0f + __expf(-(r.y + Wo_b[col + 1])));
            r.z = 1.0f / (1.0f + __expf(-(r.z + Wo_b[col + 2])));
            r.w = 1.0f / (1.0f + __expf(-(r.w + Wo_b[col + 3])));
        }
        *(float4*)(Y + (size_t)(row + i) * D_SZ + col) = r;
    }
}

// ---------------- gate kernel: i_t, f_t (one warp per batch row) ------------
__global__ __launch_bounds__(256) void gates_kernel(
    const float* __restrict__ X,
    const float* __restrict__ wi_w, const float* __restrict__ wi_b,
    const float* __restrict__ wf_w, const float* __restrict__ wf_b)
{
    const int warp = threadIdx.x >> 5;
    const int lane = threadIdx.x & 31;
    const int b    = blockIdx.x * 8 + warp;

    const float4* x4  = (const float4*)(X + (size_t)b * D_SZ);
    const float4* wi4 = (const float4*)wi_w;
    const float4* wf4 = (const float4*)wf_w;

    float si = 0.f, sf = 0.f;
    #pragma unroll
    for (int r = 0; r < 4; ++r) {
        float4 x  = x4[lane + r * 32];
        float4 wi = wi4[lane + r * 32];
        float4 wf = wf4[lane + r * 32];
        si += x.x * wi.x + x.y * wi.y + x.z * wi.z + x.w * wi.w;
        sf += x.x * wf.x + x.y * wf.y + x.z * wf.z + x.w * wf.w;
    }
    #pragma unroll
    for (int o = 16; o; o >>= 1) {
        si += __shfl_down_sync(0xffffffffu, si, o);
        sf += __shfl_down_sync(0xffffffffu, sf, o);
    }
    if (lane == 0) {
        g_it[b] = fminf(expf(si + wi_b[0]), 50.0f);
        g_ft[b] = 1.0f / (1.0f + expf(-(sf + wf_b[0])));
    }
}

// ---------------- fused cell kernel: C_t + h_tilde partial ------------------
// grid(32, 256): 16 rows per block, 16 threads per row, float4 streaming.
__global__ __launch_bounds__(256) void cell_kernel(
    const float* __restrict__ Cprev, float* __restrict__ Ct)
{
    __shared__ __align__(16) float sk[D_SZ];
    __shared__ __align__(16) float sq[D_SZ];
    __shared__ float sv[16];

    const int b   = blockIdx.y;
    const int rb  = blockIdx.x;       // row block 0..31
    const int tid = threadIdx.x;      // 0..255

    if (tid < 128) {
        ((float4*)sk)[tid] = ((const float4*)(g_k + (size_t)b * D_SZ))[tid];
    } else {
        ((float4*)sq)[tid - 128] = ((const float4*)(g_q + (size_t)b * D_SZ))[tid - 128];
    }
    if (tid < 16) sv[tid] = g_v[(size_t)b * D_SZ + rb * 16 + tid];
    __syncthreads();

    const float f  = g_ft[b];
    const float it = g_it[b];
    const int r      = tid >> 4;       // local row 0..15
    const int lane16 = tid & 15;
    const int row    = rb * 16 + r;
    const float ivi  = it * sv[r];

    const float4* cp = (const float4*)(Cprev + (size_t)b * D_SZ * D_SZ + (size_t)row * D_SZ);
    float4*       ct = (float4*)(Ct   + (size_t)b * D_SZ * D_SZ + (size_t)row * D_SZ);
    const float4* k4 = (const float4*)sk;
    const float4* q4 = (const float4*)sq;

    float ht = 0.f;
    #pragma unroll
    for (int j = 0; j < 8; ++j) {
        const int idx = lane16 + j * 16;
        float4 c  = __ldcs(cp + idx);          // stream: no reuse
        float4 kv = k4[idx];
        float4 qv = q4[idx];
        float4 o;
        o.x = f * c.x + ivi * kv.x;
        o.y = f * c.y + ivi * kv.y;
        o.z = f * c.z + ivi * kv.z;
        o.w = f * c.w + ivi * kv.w;
        __stcs(ct + idx, o);                   // stream: no reuse
        ht += o.x * qv.x + o.y * qv.y + o.z * qv.z + o.w * qv.w;
    }
    #pragma unroll
    for (int off = 8; off; off >>= 1)
        ht += __shfl_down_sync(0xffffffffu, ht, off, 16);
    if (lane16 == 0) g_ht[(size_t)b * D_SZ + row] = ht;
}

// ---------------- epilogue: warp-per-row, shfl-only reductions -------------
// 32 blocks x 256 threads; warp w handles batch row b = blk*8 + w.
// Each lane owns 16 elements (4 x float4). No __syncthreads at all.
__device__ __forceinline__ float warp_allsum(float v)
{
    #pragma unroll
    for (int o = 16; o; o >>= 1) v += __shfl_xor_sync(0xffffffffu, v, o);
    return v;
}

__global__ __launch_bounds__(256) void epilogue_kernel(
    const float* __restrict__ n_prev,
    const float* __restrict__ ln_g, const float* __restrict__ ln_b,
    float* __restrict__ out_h, float* __restrict__ out_n)
{
    const int warp = threadIdx.x >> 5;
    const int lane = threadIdx.x & 31;
    const int b    = blockIdx.x * 8 + warp;
    const size_t base = (size_t)b * D_SZ;

    const float f  = g_ft[b];
    const float it = g_it[b];

    const float4* np4 = (const float4*)(n_prev + base);
    const float4* k4  = (const float4*)(g_k + base);
    const float4* q4  = (const float4*)(g_q + base);
    const float4* o4  = (const float4*)(g_o + base);
    const float4* ht4 = (const float4*)(g_ht + base);
    const float4* g4  = (const float4*)ln_g;
    const float4* bb4 = (const float4*)ln_b;
    float4* on4 = (float4*)(out_n + base);
    float4* oh4 = (float4*)(out_h + base);

    // pass 1: n_t, nq
    float nq = 0.f;
    #pragma unroll
    for (int r = 0; r < 4; ++r) {
        const int i = lane + r * 32;
        float4 np = np4[i], k = k4[i], q = q4[i];
        float4 nt;
        nt.x = f * np.x + it * k.x;
        nt.y = f * np.y + it * k.y;
        nt.z = f * np.z + it * k.z;
        nt.w = f * np.w + it * k.w;
        on4[i] = nt;
        nq += nt.x * q.x + nt.y * q.y + nt.z * q.z + nt.w * q.w;
    }
    nq = warp_allsum(nq);
    const float inv_den = 1.0f / fmaxf(fabsf(nq), 1.0f);

    // pass 2: h, mean
    float4 h[4];
    float mu = 0.f;
    #pragma unroll
    for (int r = 0; r < 4; ++r) {
        const int i = lane + r * 32;
        float4 o = o4[i], t = ht4[i];
        h[r].x = o.x * t.x * inv_den;
        h[r].y = o.y * t.y * inv_den;
        h[r].z = o.z * t.z * inv_den;
        h[r].w = o.w * t.w * inv_den;
        mu += h[r].x + h[r].y + h[r].z + h[r].w;
    }
    mu = warp_allsum(mu) * (1.0f / (float)D_SZ);

    // pass 3: variance
    float var = 0.f;
    #pragma unroll
    for (int r = 0; r < 4; ++r) {
        float dx = h[r].x - mu, dy = h[r].y - mu, dz = h[r].z - mu, dw = h[r].w - mu;
        var += dx * dx + dy * dy + dz * dz + dw * dw;
    }
    var = warp_allsum(var) * (1.0f / (float)D_SZ);
    const float rstd = rsqrtf(var + 1e-5f);

    // pass 4: normalize + affine
    #pragma unroll
    for (int r = 0; r < 4; ++r) {
        const int i = lane + r * 32;
        float4 g = g4[i], bb = bb4[i], o;
        o.x = (h[r].x - mu) * rstd * g.x + bb.x;
        o.y = (h[r].y - mu) * rstd * g.y + bb.y;
        o.z = (h[r].z - mu) * rstd * g.z + bb.z;
        o.w = (h[r].w - mu) * rstd * g.w + bb.w;
        oh4[i] = o;
    }
}

// ---------------- launch ----------------------------------------------------
extern "C" void kernel_launch(void* const* d_in, const int* in_sizes, int n_in,
                              void* d_out, int out_size)
{
    const float* x_t    = (const float*)d_in[0];
    const float* C_prev = (const float*)d_in[1];
    const float* n_prev = (const float*)d_in[2];
    const float* Wq     = (const float*)d_in[3];
    const float* Wk     = (const float*)d_in[4];
    const float* Wv     = (const float*)d_in[5];
    const float* wi_w   = (const float*)d_in[6];
    const float* wi_b   = (const float*)d_in[7];
    const float* wf_w   = (const float*)d_in[8];
    const float* wf_b   = (const float*)d_in[9];
    const float* Wo     = (const float*)d_in[10];
    const float* Wo_b   = (const float*)d_in[11];
    const float* ln_g   = (const float*)d_in[12];
    const float* ln_b   = (const float*)d_in[13];

    float* out   = (float*)d_out;
    float* out_h = out;                                       // [256,512]
    float* out_C = out + (size_t)B_SZ * D_SZ;                 // [256,512,512]
    float* out_n = out + (size_t)B_SZ * D_SZ + (size_t)B_SZ * D_SZ * D_SZ; // [256,512]

    gates_kernel<<<B_SZ / 8, 256>>>(x_t, wi_w, wi_b, wf_w, wf_b);
    dim3 ggrid(D_SZ / BN, B_SZ / BM, 4);                      // (8,8,4) = 256 blocks
    proj_gemm<<<ggrid, 256>>>(x_t, Wq, Wk, Wv, Wo, Wo_b);
    cell_kernel<<<dim3(D_SZ / 16, B_SZ), 256>>>(C_prev, out_C);
    epilogue_kernel<<<B_SZ / 8, 256>>>(n_prev, ln_g, ln_b, out_h, out_n);
}

// round 6
// speedup vs baseline: 1.1031x; 1.1031x over previous
#include <cuda_runtime.h>
#include <cuda_bf16.h>
#include <math.h>

#define B_SZ 256
#define D_SZ 512

// ---------------- scratch (device globals; no allocation allowed) ----------
__device__ float g_q[B_SZ * D_SZ];
__device__ float g_k[B_SZ * D_SZ];
__device__ float g_v[B_SZ * D_SZ];
__device__ float g_o[B_SZ * D_SZ];
__device__ float g_it[B_SZ];
__device__ float g_ft[B_SZ];
__device__ float g_ht[B_SZ * D_SZ];

// ---------------- projection GEMM + gates -----------------------------------
// z<4:  Y[256,512] = X[256,512] @ W[512,512]^T  (BM=64,BN=64,BK=16, 4x4/thread)
// z==4: gate kernel (one warp per batch row), reuses the same launch.
#define BM 64
#define BN 64
#define BK 16

__global__ __launch_bounds__(256) void proj_gemm(
    const float* __restrict__ X,
    const float* __restrict__ Wq, const float* __restrict__ Wk,
    const float* __restrict__ Wv, const float* __restrict__ Wo,
    const float* __restrict__ Wo_b,
    const float* __restrict__ wi_w, const float* __restrict__ wi_b,
    const float* __restrict__ wf_w, const float* __restrict__ wf_b)
{
    // ---- z==4: gates (32 blocks x 8 warps = 256 warps = 1/batch row) ----
    if (blockIdx.z == 4) {
        const int warp = threadIdx.x >> 5;
        const int lane = threadIdx.x & 31;
        const int b    = (blockIdx.y * 8 + blockIdx.x) * 8 + warp;

        const float4* x4  = (const float4*)(X + (size_t)b * D_SZ);
        const float4* wi4 = (const float4*)wi_w;
        const float4* wf4 = (const float4*)wf_w;

        float si = 0.f, sf = 0.f;
        #pragma unroll
        for (int r = 0; r < 4; ++r) {
            float4 x  = x4[lane + r * 32];
            float4 wi = wi4[lane + r * 32];
            float4 wf = wf4[lane + r * 32];
            si += x.x * wi.x + x.y * wi.y + x.z * wi.z + x.w * wi.w;
            sf += x.x * wf.x + x.y * wf.y + x.z * wf.z + x.w * wf.w;
        }
        #pragma unroll
        for (int o = 16; o; o >>= 1) {
            si += __shfl_down_sync(0xffffffffu, si, o);
            sf += __shfl_down_sync(0xffffffffu, sf, o);
        }
        if (lane == 0) {
            g_it[b] = fminf(expf(si + wi_b[0]), 50.0f);
            g_ft[b] = 1.0f / (1.0f + expf(-(sf + wf_b[0])));
        }
        return;
    }

    // ---- z<4: GEMM ----
    const float* W;
    float* Y;
    bool act = false;
    switch (blockIdx.z) {
        case 0: W = Wq; Y = g_q; break;
        case 1: W = Wk; Y = g_k; break;
        case 2: W = Wv; Y = g_v; break;
        default: W = Wo; Y = g_o; act = true; break;
    }

    __shared__ __align__(16) float As[2][BK][BM];
    __shared__ __align__(16) float Bs[2][BK][BN];

    const int tid  = threadIdx.x;
    const int m0   = blockIdx.y * BM;
    const int n0   = blockIdx.x * BN;
    const int lrow = tid >> 2;          // 0..63
    const int lcol = (tid & 3) * 4;     // 0,4,8,12

    const float* Aptr = X + (size_t)(m0 + lrow) * D_SZ + lcol;
    const float* Bptr = W + (size_t)(n0 + lrow) * D_SZ + lcol;

    // preload tile 0
    float4 a = *(const float4*)Aptr;
    float4 b = *(const float4*)Bptr;
    As[0][lcol + 0][lrow] = a.x; As[0][lcol + 1][lrow] = a.y;
    As[0][lcol + 2][lrow] = a.z; As[0][lcol + 3][lrow] = a.w;
    Bs[0][lcol + 0][lrow] = b.x; Bs[0][lcol + 1][lrow] = b.y;
    Bs[0][lcol + 2][lrow] = b.z; Bs[0][lcol + 3][lrow] = b.w;
    __syncthreads();

    const int tx = tid & 15;   // n subtile
    const int ty = tid >> 4;   // m subtile
    float acc[4][4] = {};

    const int KT = D_SZ / BK;  // 32
    int buf = 0;
    for (int t = 0; t < KT; ++t) {
        float4 na, nb;
        if (t + 1 < KT) {
            na = *(const float4*)(Aptr + (t + 1) * BK);
            nb = *(const float4*)(Bptr + (t + 1) * BK);
        }
        #pragma unroll
        for (int kk = 0; kk < BK; ++kk) {
            float4 av = *(const float4*)&As[buf][kk][ty * 4];
            float4 bv = *(const float4*)&Bs[buf][kk][tx * 4];
            acc[0][0] += av.x * bv.x; acc[0][1] += av.x * bv.y;
            acc[0][2] += av.x * bv.z; acc[0][3] += av.x * bv.w;
            acc[1][0] += av.y * bv.x; acc[1][1] += av.y * bv.y;
            acc[1][2] += av.y * bv.z; acc[1][3] += av.y * bv.w;
            acc[2][0] += av.z * bv.x; acc[2][1] += av.z * bv.y;
            acc[2][2] += av.z * bv.z; acc[2][3] += av.z * bv.w;
            acc[3][0] += av.w * bv.x; acc[3][1] += av.w * bv.y;
            acc[3][2] += av.w * bv.z; acc[3][3] += av.w * bv.w;
        }
        if (t + 1 < KT) {
            int nbuf = buf ^ 1;
            As[nbuf][lcol + 0][lrow] = na.x; As[nbuf][lcol + 1][lrow] = na.y;
            As[nbuf][lcol + 2][lrow] = na.z; As[nbuf][lcol + 3][lrow] = na.w;
            Bs[nbuf][lcol + 0][lrow] = nb.x; Bs[nbuf][lcol + 1][lrow] = nb.y;
            Bs[nbuf][lcol + 2][lrow] = nb.z; Bs[nbuf][lcol + 3][lrow] = nb.w;
        }
        __syncthreads();
        buf ^= 1;
    }

    const int row = m0 + ty * 4;
    const int col = n0 + tx * 4;
    #pragma unroll
    for (int i = 0; i < 4; ++i) {
        float4 r;
        r.x = acc[i][0]; r.y = acc[i][1]; r.z = acc[i][2]; r.w = acc[i][3];
        if (act) {
            r.x = 1.0f / (1.0f + __expf(-(r.x + Wo_b[col + 0])));
            r.y = 1.0f / (1.0f + __expf(-(r.y + Wo_b[col + 1])));
            r.z = 1.0f / (1.0f + __expf(-(r.z + Wo_b[col + 2])));
            r.w = 1.0f / (1.0f + __expf(-(r.w + Wo_b[col + 3])));
        }
        *(float4*)(Y + (size_t)(row + i) * D_SZ + col) = r;
    }
}

// ---------------- fused cell kernel: C_t + h_tilde partial ------------------
// grid(32, 256): 16 rows per block, 16 threads per row, float4 streaming.
__global__ __launch_bounds__(256) void cell_kernel(
    const float* __restrict__ Cprev, float* __restrict__ Ct)
{
    __shared__ __align__(16) float sk[D_SZ];
    __shared__ __align__(16) float sq[D_SZ];
    __shared__ float sv[16];

    const int b   = blockIdx.y;
    const int rb  = blockIdx.x;       // row block 0..31
    const int tid = threadIdx.x;      // 0..255

    if (tid < 128) {
        ((float4*)sk)[tid] = ((const float4*)(g_k + (size_t)b * D_SZ))[tid];
    } else {
        ((float4*)sq)[tid - 128] = ((const float4*)(g_q + (size_t)b * D_SZ))[tid - 128];
    }
    if (tid < 16) sv[tid] = g_v[(size_t)b * D_SZ + rb * 16 + tid];
    __syncthreads();

    const float f  = g_ft[b];
    const float it = g_it[b];
    const int r      = tid >> 4;       // local row 0..15
    const int lane16 = tid & 15;
    const int row    = rb * 16 + r;
    const float ivi  = it * sv[r];

    const float4* cp = (const float4*)(Cprev + (size_t)b * D_SZ * D_SZ + (size_t)row * D_SZ);
    float4*       ct = (float4*)(Ct   + (size_t)b * D_SZ * D_SZ + (size_t)row * D_SZ);
    const float4* k4 = (const float4*)sk;
    const float4* q4 = (const float4*)sq;

    float ht = 0.f;
    #pragma unroll
    for (int j = 0; j < 8; ++j) {
        const int idx = lane16 + j * 16;
        float4 c  = __ldcs(cp + idx);          // stream: no reuse
        float4 kv = k4[idx];
        float4 qv = q4[idx];
        float4 o;
        o.x = f * c.x + ivi * kv.x;
        o.y = f * c.y + ivi * kv.y;
        o.z = f * c.z + ivi * kv.z;
        o.w = f * c.w + ivi * kv.w;
        __stcs(ct + idx, o);                   // stream: no reuse
        ht += o.x * qv.x + o.y * qv.y + o.z * qv.z + o.w * qv.w;
    }
    #pragma unroll
    for (int off = 8; off; off >>= 1)
        ht += __shfl_down_sync(0xffffffffu, ht, off, 16);
    if (lane16 == 0) g_ht[(size_t)b * D_SZ + row] = ht;
}

// ---------------- epilogue: n_t, nq, h, LayerNorm ---------------------------
// 256 blocks x 256 threads; ALL global loads issued before first reduction;
// mean+variance fused into one packed float2 reduction (2 barrier rounds total).
__global__ __launch_bounds__(256) void epilogue_kernel(
    const float* __restrict__ n_prev,
    const float* __restrict__ ln_g, const float* __restrict__ ln_b,
    float* __restrict__ out_h, float* __restrict__ out_n)
{
    __shared__ float  red1[8];
    __shared__ float2 red2[8];

    const int b   = blockIdx.x;
    const int tid = threadIdx.x;
    const int e0  = tid;
    const int e1  = tid + 256;
    const size_t base = (size_t)b * D_SZ;

    const float f  = g_ft[b];
    const float it = g_it[b];

    // ---- issue every global load up front (overlap latency with reductions)
    const float np0 = n_prev[base + e0], np1 = n_prev[base + e1];
    const float k0  = g_k[base + e0],   k1  = g_k[base + e1];
    const float q0  = g_q[base + e0],   q1  = g_q[base + e1];
    const float o0  = g_o[base + e0],   o1  = g_o[base + e1];
    const float t0  = g_ht[base + e0],  t1  = g_ht[base + e1];
    const float gg0 = ln_g[e0],         gg1 = ln_g[e1];
    const float bb0 = ln_b[e0],         bb1 = ln_b[e1];

    const float nt0 = f * np0 + it * k0;
    const float nt1 = f * np1 + it * k1;
    out_n[base + e0] = nt0;
    out_n[base + e1] = nt1;

    // ---- reduction 1: nq
    float nq = nt0 * q0 + nt1 * q1;
    {
        #pragma unroll
        for (int o = 16; o; o >>= 1) nq += __shfl_down_sync(0xffffffffu, nq, o);
        const int w = tid >> 5;
        if ((tid & 31) == 0) red1[w] = nq;
        __syncthreads();
        if (tid < 8) {
            float s = red1[tid];
            #pragma unroll
            for (int o = 4; o; o >>= 1) s += __shfl_down_sync(0xffu, s, o);
            if (tid == 0) red1[0] = s;
        }
        __syncthreads();
        nq = red1[0];
    }
    const float inv_den = 1.0f / fmaxf(fabsf(nq), 1.0f);

    const float h0 = o0 * t0 * inv_den;
    const float h1 = o1 * t1 * inv_den;

    // ---- reduction 2 (packed): sum(h), sum(h^2)
    float s  = h0 + h1;
    float s2 = h0 * h0 + h1 * h1;
    {
        #pragma unroll
        for (int o = 16; o; o >>= 1) {
            s  += __shfl_down_sync(0xffffffffu, s,  o);
            s2 += __shfl_down_sync(0xffffffffu, s2, o);
        }
        const int w = tid >> 5;
        if ((tid & 31) == 0) red2[w] = make_float2(s, s2);
        __syncthreads();
        if (tid < 8) {
            float2 v = red2[tid];
            #pragma unroll
            for (int o = 4; o; o >>= 1) {
                v.x += __shfl_down_sync(0xffu, v.x, o);
                v.y += __shfl_down_sync(0xffu, v.y, o);
            }
            if (tid == 0) red2[0] = v;
        }
        __syncthreads();
        s  = red2[0].x;
        s2 = red2[0].y;
    }

    const float mu   = s * (1.0f / (float)D_SZ);
    const float var  = fmaxf(s2 * (1.0f / (float)D_SZ) - mu * mu, 0.0f);
    const float rstd = rsqrtf(var + 1e-5f);

    out_h[base + e0] = (h0 - mu) * rstd * gg0 + bb0;
    out_h[base + e1] = (h1 - mu) * rstd * gg1 + bb1;
}

// ---------------- launch ----------------------------------------------------
extern "C" void kernel_launch(void* const* d_in, const int* in_sizes, int n_in,
                              void* d_out, int out_size)
{
    const float* x_t    = (const float*)d_in[0];
    const float* C_prev = (const float*)d_in[1];
    const float* n_prev = (const float*)d_in[2];
    const float* Wq     = (const float*)d_in[3];
    const float* Wk     = (const float*)d_in[4];
    const float* Wv     = (const float*)d_in[5];
    const float* wi_w   = (const float*)d_in[6];
    const float* wi_b   = (const float*)d_in[7];
    const float* wf_w   = (const float*)d_in[8];
    const float* wf_b   = (const float*)d_in[9];
    const float* Wo     = (const float*)d_in[10];
    const float* Wo_b   = (const float*)d_in[11];
    const float* ln_g   = (const float*)d_in[12];
    const float* ln_b   = (const float*)d_in[13];

    float* out   = (float*)d_out;
    float* out_h = out;                                       // [256,512]
    float* out_C = out + (size_t)B_SZ * D_SZ;                 // [256,512,512]
    float* out_n = out + (size_t)B_SZ * D_SZ + (size_t)B_SZ * D_SZ * D_SZ; // [256,512]

    dim3 ggrid(D_SZ / BN, B_SZ / BM, 5);                      // (8,4,5): 4 GEMMs + gates
    proj_gemm<<<ggrid, 256>>>(x_t, Wq, Wk, Wv, Wo, Wo_b,
                              wi_w, wi_b, wf_w, wf_b);
    cell_kernel<<<dim3(D_SZ / 16, B_SZ), 256>>>(C_prev, out_C);
    epilogue_kernel<<<B_SZ, 256>>>(n_prev, ln_g, ln_b, out_h, out_n);
}